// round 9
// baseline (speedup 1.0000x reference)
#include <cuda_runtime.h>

// Correlation cost volume (FlowNet-style), MAX_DISP=4 (81 displacements).
// first, second: [B=4, C=128, H=128, W=192] fp32.  out: [B, 81, H, W] fp32,
// out[b,(dy+4)*9+(dx+4),y,x] = (1/C) * sum_c first[b,c,y,x]*second[b,c,y+dy,x+dx]
//
// v5: R7 tiling (TX=64, TY=8, 128 thr, dy-group 3) but `first` loaded straight
// into registers via LDG.128 (it is thread-private) -> smem halves to 46 KB,
// 3 blocks/SM (12 warps), plus shifted-f f32x2 packing on odd-dx taps.

namespace {
constexpr int Bb = 4, Cc = 128, Hh = 128, Ww = 192;
constexpr int PXT = 4;             // pixels per thread along x
constexpr int GX  = 16;            // thread columns
constexpr int TX  = GX * PXT;      // 64
constexpr int TY  = 8;
constexpr int NT  = GX * TY;       // 128 threads
constexpr int CCH = 8;             // channels per stage
constexpr int NST = Cc / CCH;      // 16
constexpr int SROWS = TY + 2;      // 10 second rows per dy-group of 3
constexpr int SW  = TX + 8;        // 72 floats per second row
constexpr int SROW_V4 = SW / 4;    // 18
constexpr int XT  = Ww / TX;       // 3
constexpr int YT  = Hh / TY;       // 16
constexpr int SEC_F = CCH * SROWS * SW;   // 5760 floats (second tile only)
constexpr int BUF_F = SEC_F;              // per pipeline buffer
constexpr unsigned SMEM_BYTES = 2u * BUF_F * 4u;  // 46080 B -> 3 blocks/SM
constexpr int NBLOCKS = Bb * XT * YT * 3;  // 576
constexpr int SEC_V4 = SEC_F / 4;          // 1440
constexpr int SEC_SLOTS = 12;              // 11 full + 32 threads in slot 11
constexpr int TAIL = SEC_V4 - 11 * NT;     // 32
constexpr unsigned CH_STRIDE = (unsigned)CCH * Hh * Ww * 4u;   // bytes per stage
constexpr unsigned PLANE = (unsigned)Hh * Ww * 4u;             // one channel plane
}  // namespace

__device__ __forceinline__ void cp16(unsigned sdst, const char* gsrc, unsigned sz) {
    asm volatile("cp.async.cg.shared.global [%0], [%1], 16, %2;\n"
                 :: "r"(sdst), "l"(gsrc), "r"(sz) : "memory");
}
__device__ __forceinline__ unsigned long long pack2(float x, float y) {
    unsigned long long r;
    asm("mov.b64 %0, {%1, %2};" : "=l"(r) : "f"(x), "f"(y));
    return r;
}
__device__ __forceinline__ void ffma2(unsigned long long& d,
                                      unsigned long long a, unsigned long long b) {
    asm("fma.rn.f32x2 %0, %1, %2, %0;" : "+l"(d) : "l"(a), "l"(b));
}
__device__ __forceinline__ void unpack2(unsigned long long v, float& lo, float& hi) {
    asm("mov.b64 {%0, %1}, %2;" : "=f"(lo), "=f"(hi) : "l"(v));
}

__global__ __launch_bounds__(NT, 3)
void FunctionCorrelation_17282948399394_kernel(
    const float* __restrict__ first,
    const float* __restrict__ second,
    float* __restrict__ out)
{
    extern __shared__ float smem[];
    const unsigned smem_u32 = (unsigned)__cvta_generic_to_shared(smem);

    const int tid = threadIdx.x;          // 0..127
    const int tx  = tid & 15;             // pixel quad 0..15
    const int ty  = tid >> 4;             // row 0..7

    int t = blockIdx.x;
    const int g  = t % 3;  t /= 3;        // dy group: dy in {3g-4,3g-3,3g-2}
    const int xt = t % XT; t /= XT;
    const int yt = t % YT; t /= YT;
    const int b  = t;

    const int x0  = xt * TX;
    const int y0  = yt * TY;
    const int ys0 = y0 + 3 * g - 4;

    // ---- precompute second-tile load slots (stage-0 byte offsets) -----------
    unsigned secOff[SEC_SLOTS];
    unsigned vmask = 0;                   // bit s -> in-bounds (sz=16)
#pragma unroll
    for (int s = 0; s < SEC_SLOTS; s++) {
        const int i = s * NT + tid;
        unsigned off = 0;
        if (i < SEC_V4) {
            const int ch  = i / (SROWS * SROW_V4);
            const int rem = i - ch * (SROWS * SROW_V4);
            const int r   = rem / SROW_V4;
            const int k   = rem - r * SROW_V4;
            const int gy  = ys0 + r;
            const int gx  = x0 - 4 + 4 * k;
            if ((unsigned)gy < (unsigned)Hh && (unsigned)gx < (unsigned)Ww) {
                off = (unsigned)((((b * Cc + ch) * Hh + gy) * Ww + gx) * 4);
                vmask |= 1u << s;
            }
        }
        secOff[s] = off;
    }

    const char* secP = (const char*)second;
    // first: thread-private float4 per channel (row y0+ty, quad tx)
    const float4* fstP = (const float4*)(first +
        (((size_t)b * Cc * Hh + (y0 + ty)) * Ww + x0 + 4 * tx));
    const size_t FPL = (size_t)Hh * Ww / 4;   // float4s per channel plane

    auto issue_stage = [&](int buf, const char* sp) {
        const unsigned sbase = smem_u32 + (unsigned)buf * (BUF_F * 4u);
#pragma unroll
        for (int s = 0; s < SEC_SLOTS; s++) {
            if (s < SEC_SLOTS - 1 || tid < TAIL)
                cp16(sbase + (unsigned)(s * NT + tid) * 16u, sp + secOff[s],
                     ((vmask >> s) & 1u) ? 16u : 0u);
        }
        asm volatile("cp.async.commit_group;" ::: "memory");
    };

    // ---- accumulators --------------------------------------------------------
    unsigned long long acc2[3][5][2];   // even dx=2q: [j][q][pixel-pair]
    unsigned long long accm[3][4];      // odd dx=2o+1, middle pixels (f.y,f.z)
    float acce[3][4][2];                // odd dx edges: pixel 0 / pixel 3
#pragma unroll
    for (int j = 0; j < 3; j++) {
#pragma unroll
        for (int q = 0; q < 5; q++) { acc2[j][q][0] = 0ull; acc2[j][q][1] = 0ull; }
#pragma unroll
        for (int o = 0; o < 4; o++) {
            accm[j][o] = 0ull; acce[j][o][0] = 0.f; acce[j][o][1] = 0.f;
        }
    }

    // ---- pipelined main loop ------------------------------------------------
    issue_stage(0, secP);
    secP += CH_STRIDE;

#pragma unroll 1
    for (int st = 0; st < NST; st++) {
        if (st + 1 < NST) {
            issue_stage((st + 1) & 1, secP);
            secP += CH_STRIDE;
        }
        // first-tile registers for THIS stage (LDG latency overlaps wait+sync)
        float4 fr[CCH];
#pragma unroll
        for (int ch = 0; ch < CCH; ch++)
            fr[ch] = __ldg(fstP + ((size_t)(st * CCH + ch)) * FPL);

        if (st + 1 < NST)
            asm volatile("cp.async.wait_group 1;" ::: "memory");
        else
            asm volatile("cp.async.wait_group 0;" ::: "memory");
        __syncthreads();

        const float4* secb = (const float4*)(smem + (st & 1) * BUF_F);

#pragma unroll
        for (int ch = 0; ch < CCH; ch++) {
            const float4 f = fr[ch];
            const unsigned long long fp0 = pack2(f.x, f.y);
            const unsigned long long fp1 = pack2(f.z, f.w);
            const unsigned long long fps = pack2(f.y, f.z);   // shifted pair
#pragma unroll
            for (int j = 0; j < 3; j++) {
                const float4* sr = secb + (ch * SROWS + ty + j) * SROW_V4 + tx;
                const float4 a = sr[0], c = sr[1], e = sr[2];
                const unsigned long long P0 = pack2(a.x, a.y);
                const unsigned long long P1 = pack2(a.z, a.w);
                const unsigned long long P2 = pack2(c.x, c.y);
                const unsigned long long P3 = pack2(c.z, c.w);
                const unsigned long long P4 = pack2(e.x, e.y);
                const unsigned long long P5 = pack2(e.z, e.w);
                // even dx=2q: pair0 (p0,p1) uses P_q, pair1 (p2,p3) uses P_{q+1}
                ffma2(acc2[j][0][0], fp0, P0);  ffma2(acc2[j][0][1], fp1, P1);
                ffma2(acc2[j][1][0], fp0, P1);  ffma2(acc2[j][1][1], fp1, P2);
                ffma2(acc2[j][2][0], fp0, P2);  ffma2(acc2[j][2][1], fp1, P3);
                ffma2(acc2[j][3][0], fp0, P3);  ffma2(acc2[j][3][1], fp1, P4);
                ffma2(acc2[j][4][0], fp0, P4);  ffma2(acc2[j][4][1], fp1, P5);
                // odd dx=2o+1: middle pixels (1,2) = (f.y,f.z)*(s[2o+2],s[2o+3])
                ffma2(accm[j][0], fps, P1);
                ffma2(accm[j][1], fps, P2);
                ffma2(accm[j][2], fps, P3);
                ffma2(accm[j][3], fps, P4);
                // odd dx edges: p0 += f.x*s[2o+1], p3 += f.w*s[2o+4]
                acce[j][0][0] += f.x * a.y;  acce[j][0][1] += f.w * c.x;
                acce[j][1][0] += f.x * a.w;  acce[j][1][1] += f.w * c.z;
                acce[j][2][0] += f.x * c.y;  acce[j][2][1] += f.w * e.x;
                acce[j][3][0] += f.x * c.w;  acce[j][3][1] += f.w * e.z;
            }
        }
        __syncthreads();   // buffer reads done before it is refilled next iter
    }

    // ---- epilogue: 27 planes x 4 pixels, float4 stores ----------------------
    const float inv = 1.0f / (float)Cc;
    const int x = x0 + tx * PXT;
    const int y = y0 + ty;
#pragma unroll
    for (int j = 0; j < 3; j++) {
        const int dyi = 3 * g + j;
#pragma unroll
        for (int q = 0; q < 5; q++) {              // dx index 2q
            float v0, v1, v2, v3;
            unpack2(acc2[j][q][0], v0, v1);
            unpack2(acc2[j][q][1], v2, v3);
            const int d = dyi * 9 + 2 * q;
            *reinterpret_cast<float4*>(out + ((b * 81 + d) * Hh + y) * Ww + x) =
                make_float4(v0 * inv, v1 * inv, v2 * inv, v3 * inv);
        }
#pragma unroll
        for (int o = 0; o < 4; o++) {              // dx index 2o+1
            float m1, m2;
            unpack2(accm[j][o], m1, m2);
            const int d = dyi * 9 + 2 * o + 1;
            *reinterpret_cast<float4*>(out + ((b * 81 + d) * Hh + y) * Ww + x) =
                make_float4(acce[j][o][0] * inv, m1 * inv,
                            m2 * inv,            acce[j][o][1] * inv);
        }
    }
}

extern "C" void kernel_launch(void* const* d_in, const int* in_sizes, int n_in,
                              void* d_out, int out_size)
{
    const float* first  = (const float*)d_in[0];
    const float* second = (const float*)d_in[1];
    float* out          = (float*)d_out;

    cudaFuncSetAttribute(FunctionCorrelation_17282948399394_kernel,
                         cudaFuncAttributeMaxDynamicSharedMemorySize,
                         (int)SMEM_BYTES);

    FunctionCorrelation_17282948399394_kernel<<<NBLOCKS, NT, SMEM_BYTES>>>(
        first, second, out);
}

// round 10
// speedup vs baseline: 1.2686x; 1.2686x over previous
#include <cuda_runtime.h>

// Correlation cost volume (FlowNet-style), MAX_DISP=4 (81 displacements).
// first, second: [B=4, C=128, H=128, W=192] fp32.  out: [B, 81, H, W] fp32,
// out[b,(dy+4)*9+(dx+4),y,x] = (1/C) * sum_c first[b,c,y,x]*second[b,c,y+dy,x+dx]
//
// v6: R7 tiling (TX=64, TY=8, 128 thr, dy-group 3); `first` in registers
// (LDG.128 per stage, issued before the cp.async wait); sec-only smem 46 KB;
// __launch_bounds__(128,2) so NO register cap (R9's 170-cap caused spills);
// shifted-f f32x2 packing on odd-dx taps.

namespace {
constexpr int Bb = 4, Cc = 128, Hh = 128, Ww = 192;
constexpr int PXT = 4;             // pixels per thread along x
constexpr int GX  = 16;            // thread columns
constexpr int TX  = GX * PXT;      // 64
constexpr int TY  = 8;
constexpr int NT  = GX * TY;       // 128 threads
constexpr int CCH = 8;             // channels per stage
constexpr int NST = Cc / CCH;      // 16
constexpr int SROWS = TY + 2;      // 10 second rows per dy-group of 3
constexpr int SW  = TX + 8;        // 72 floats per second row
constexpr int SROW_V4 = SW / 4;    // 18
constexpr int XT  = Ww / TX;       // 3
constexpr int YT  = Hh / TY;       // 16
constexpr int SEC_F = CCH * SROWS * SW;   // 5760 floats (second tile only)
constexpr int BUF_F = SEC_F;
constexpr unsigned SMEM_BYTES = 2u * BUF_F * 4u;  // 46080 B
constexpr int NBLOCKS = Bb * XT * YT * 3;  // 576
constexpr int SEC_V4 = SEC_F / 4;          // 1440
constexpr int SEC_SLOTS = 12;              // 11 full + 32-thread tail
constexpr int TAIL = SEC_V4 - 11 * NT;     // 32
constexpr unsigned CH_STRIDE = (unsigned)CCH * Hh * Ww * 4u;   // bytes per stage
}  // namespace

__device__ __forceinline__ void cp16(unsigned sdst, const char* gsrc, unsigned sz) {
    asm volatile("cp.async.cg.shared.global [%0], [%1], 16, %2;\n"
                 :: "r"(sdst), "l"(gsrc), "r"(sz) : "memory");
}
__device__ __forceinline__ unsigned long long pack2(float x, float y) {
    unsigned long long r;
    asm("mov.b64 %0, {%1, %2};" : "=l"(r) : "f"(x), "f"(y));
    return r;
}
__device__ __forceinline__ void ffma2(unsigned long long& d,
                                      unsigned long long a, unsigned long long b) {
    asm("fma.rn.f32x2 %0, %1, %2, %0;" : "+l"(d) : "l"(a), "l"(b));
}
__device__ __forceinline__ void unpack2(unsigned long long v, float& lo, float& hi) {
    asm("mov.b64 {%0, %1}, %2;" : "=f"(lo), "=f"(hi) : "l"(v));
}

__global__ __launch_bounds__(NT, 2)     // min 2 blocks/SM; NO tight reg cap
void FunctionCorrelation_17282948399394_kernel(
    const float* __restrict__ first,
    const float* __restrict__ second,
    float* __restrict__ out)
{
    extern __shared__ float smem[];
    const unsigned smem_u32 = (unsigned)__cvta_generic_to_shared(smem);

    const int tid = threadIdx.x;          // 0..127
    const int tx  = tid & 15;             // pixel quad 0..15
    const int ty  = tid >> 4;             // row 0..7

    int t = blockIdx.x;
    const int g  = t % 3;  t /= 3;        // dy group: dy in {3g-4,3g-3,3g-2}
    const int xt = t % XT; t /= XT;
    const int yt = t % YT; t /= YT;
    const int b  = t;

    const int x0  = xt * TX;
    const int y0  = yt * TY;
    const int ys0 = y0 + 3 * g - 4;

    // ---- precompute second-tile load slots (stage-0 byte offsets) -----------
    unsigned secOff[SEC_SLOTS];
    unsigned vmask = 0;                   // bit s -> in-bounds (sz=16)
#pragma unroll
    for (int s = 0; s < SEC_SLOTS; s++) {
        const int i = s * NT + tid;
        unsigned off = 0;
        if (i < SEC_V4) {
            const int ch  = i / (SROWS * SROW_V4);
            const int rem = i - ch * (SROWS * SROW_V4);
            const int r   = rem / SROW_V4;
            const int k   = rem - r * SROW_V4;
            const int gy  = ys0 + r;
            const int gx  = x0 - 4 + 4 * k;
            if ((unsigned)gy < (unsigned)Hh && (unsigned)gx < (unsigned)Ww) {
                off = (unsigned)((((b * Cc + ch) * Hh + gy) * Ww + gx) * 4);
                vmask |= 1u << s;
            }
        }
        secOff[s] = off;
    }

    const char* secP = (const char*)second;
    // first: thread-private float4 per channel (row y0+ty, quad tx)
    const float4* fstP = (const float4*)(first +
        (((size_t)b * Cc * Hh + (y0 + ty)) * Ww + x0 + 4 * tx));
    const size_t FPL = (size_t)Hh * Ww / 4;   // float4s per channel plane

    auto issue_stage = [&](int buf, const char* sp) {
        const unsigned sbase = smem_u32 + (unsigned)buf * (BUF_F * 4u);
#pragma unroll
        for (int s = 0; s < SEC_SLOTS; s++) {
            if (s < SEC_SLOTS - 1 || tid < TAIL)
                cp16(sbase + (unsigned)(s * NT + tid) * 16u, sp + secOff[s],
                     ((vmask >> s) & 1u) ? 16u : 0u);
        }
        asm volatile("cp.async.commit_group;" ::: "memory");
    };

    // ---- accumulators --------------------------------------------------------
    unsigned long long acc2[3][5][2];   // even dx=2q: [j][q][pixel-pair]
    unsigned long long accm[3][4];      // odd dx=2o+1, middle pixels (f.y,f.z)
    float acce[3][4][2];                // odd dx edges: pixel 0 / pixel 3
#pragma unroll
    for (int j = 0; j < 3; j++) {
#pragma unroll
        for (int q = 0; q < 5; q++) { acc2[j][q][0] = 0ull; acc2[j][q][1] = 0ull; }
#pragma unroll
        for (int o = 0; o < 4; o++) {
            accm[j][o] = 0ull; acce[j][o][0] = 0.f; acce[j][o][1] = 0.f;
        }
    }

    // ---- pipelined main loop ------------------------------------------------
    issue_stage(0, secP);
    secP += CH_STRIDE;

#pragma unroll 1
    for (int st = 0; st < NST; st++) {
        // first-tile registers for THIS stage: issue LDGs first (consumed right
        // after the sync), then next stage's cp.async, then wait.
        float4 fr[CCH];
#pragma unroll
        for (int ch = 0; ch < CCH; ch++)
            fr[ch] = __ldg(fstP + ((size_t)(st * CCH + ch)) * FPL);

        if (st + 1 < NST) {
            issue_stage((st + 1) & 1, secP);
            secP += CH_STRIDE;
            asm volatile("cp.async.wait_group 1;" ::: "memory");
        } else {
            asm volatile("cp.async.wait_group 0;" ::: "memory");
        }
        __syncthreads();

        const float4* secb = (const float4*)(smem + (st & 1) * BUF_F);

#pragma unroll
        for (int ch = 0; ch < CCH; ch++) {
            const float4 f = fr[ch];
            const unsigned long long fp0 = pack2(f.x, f.y);
            const unsigned long long fp1 = pack2(f.z, f.w);
            const unsigned long long fps = pack2(f.y, f.z);   // shifted pair
#pragma unroll
            for (int j = 0; j < 3; j++) {
                const float4* sr = secb + (ch * SROWS + ty + j) * SROW_V4 + tx;
                const float4 a = sr[0], c = sr[1], e = sr[2];
                // s[0..11] = a.x a.y a.z a.w  c.x c.y c.z c.w  e.x e.y e.z e.w
                const unsigned long long P0 = pack2(a.x, a.y);
                const unsigned long long P1 = pack2(a.z, a.w);
                const unsigned long long P2 = pack2(c.x, c.y);
                const unsigned long long P3 = pack2(c.z, c.w);
                const unsigned long long P4 = pack2(e.x, e.y);
                const unsigned long long P5 = pack2(e.z, e.w);
                // even dx=2q: pair0 (p0,p1) uses P_q, pair1 (p2,p3) uses P_{q+1}
                ffma2(acc2[j][0][0], fp0, P0);  ffma2(acc2[j][0][1], fp1, P1);
                ffma2(acc2[j][1][0], fp0, P1);  ffma2(acc2[j][1][1], fp1, P2);
                ffma2(acc2[j][2][0], fp0, P2);  ffma2(acc2[j][2][1], fp1, P3);
                ffma2(acc2[j][3][0], fp0, P3);  ffma2(acc2[j][3][1], fp1, P4);
                ffma2(acc2[j][4][0], fp0, P4);  ffma2(acc2[j][4][1], fp1, P5);
                // odd dx=2o+1: middle pixels (1,2) = (f.y,f.z)*(s[2o+2],s[2o+3])
                ffma2(accm[j][0], fps, P1);
                ffma2(accm[j][1], fps, P2);
                ffma2(accm[j][2], fps, P3);
                ffma2(accm[j][3], fps, P4);
                // odd dx edges: p0 += f.x*s[2o+1], p3 += f.w*s[2o+4]
                acce[j][0][0] += f.x * a.y;  acce[j][0][1] += f.w * c.x;
                acce[j][1][0] += f.x * a.w;  acce[j][1][1] += f.w * c.z;
                acce[j][2][0] += f.x * c.y;  acce[j][2][1] += f.w * e.x;
                acce[j][3][0] += f.x * c.w;  acce[j][3][1] += f.w * e.z;
            }
        }
        __syncthreads();   // buffer reads done before it is refilled next iter
    }

    // ---- epilogue: 27 planes x 4 pixels, float4 stores ----------------------
    const float inv = 1.0f / (float)Cc;
    const int x = x0 + tx * PXT;
    const int y = y0 + ty;
#pragma unroll
    for (int j = 0; j < 3; j++) {
        const int dyi = 3 * g + j;
#pragma unroll
        for (int q = 0; q < 5; q++) {              // dx index 2q
            float v0, v1, v2, v3;
            unpack2(acc2[j][q][0], v0, v1);
            unpack2(acc2[j][q][1], v2, v3);
            const int d = dyi * 9 + 2 * q;
            *reinterpret_cast<float4*>(out + ((b * 81 + d) * Hh + y) * Ww + x) =
                make_float4(v0 * inv, v1 * inv, v2 * inv, v3 * inv);
        }
#pragma unroll
        for (int o = 0; o < 4; o++) {              // dx index 2o+1
            float m1, m2;
            unpack2(accm[j][o], m1, m2);
            const int d = dyi * 9 + 2 * o + 1;
            *reinterpret_cast<float4*>(out + ((b * 81 + d) * Hh + y) * Ww + x) =
                make_float4(acce[j][o][0] * inv, m1 * inv,
                            m2 * inv,            acce[j][o][1] * inv);
        }
    }
}

extern "C" void kernel_launch(void* const* d_in, const int* in_sizes, int n_in,
                              void* d_out, int out_size)
{
    const float* first  = (const float*)d_in[0];
    const float* second = (const float*)d_in[1];
    float* out          = (float*)d_out;

    cudaFuncSetAttribute(FunctionCorrelation_17282948399394_kernel,
                         cudaFuncAttributeMaxDynamicSharedMemorySize,
                         (int)SMEM_BYTES);

    FunctionCorrelation_17282948399394_kernel<<<NBLOCKS, NT, SMEM_BYTES>>>(
        first, second, out);
}